// round 7
// baseline (speedup 1.0000x reference)
#include <cuda_runtime.h>
#include <cuda_bf16.h>
#include <cstdint>

// Problem dims (fixed)
#define BB 8
#define CC 128
#define AA 16
#define NNPIX 4096   // W*H

// ---------------- scratch (device globals; no alloc allowed) ----------------
// Packed bf16 hi/lo rows: [b][n][16 hi | 16 lo bf16] = 64B per row -> 4 uint4
__device__ uint4 g_qpack[(size_t)BB * NNPIX * 4];
__device__ uint4 g_kpack[(size_t)BB * NNPIX * 4];
// V transposed bf16: [b][c][n], hi and lo planes (8MB each)
__device__ uint4 g_vth[(size_t)BB * CC * NNPIX / 8];
__device__ uint4 g_vtl[(size_t)BB * CC * NNPIX / 8];

// ---------------- helpers ----------------
__device__ __forceinline__ uint32_t smem_to_u32(const void* p) {
    uint32_t a;
    asm("{ .reg .u64 t; cvta.to.shared.u64 t, %1; cvt.u32.u64 %0, t; }" : "=r"(a) : "l"(p));
    return a;
}
__device__ __forceinline__ float ex2(float x) {
    float r; asm("ex2.approx.f32 %0, %1;" : "=f"(r) : "f"(x)); return r;
}
__device__ __forceinline__ void ldsm_x4(uint32_t addr, uint32_t* r) {
    asm volatile("ldmatrix.sync.aligned.m8n8.x4.shared.b16 {%0,%1,%2,%3}, [%4];"
        : "=r"(r[0]), "=r"(r[1]), "=r"(r[2]), "=r"(r[3]) : "r"(addr));
}
// d += A(bf16) * B(bf16), fp32 accum, m16n8k16
__device__ __forceinline__ void mma16816(float* d, const uint32_t* a, const uint32_t* b) {
    asm volatile("mma.sync.aligned.m16n8k16.row.col.f32.bf16.bf16.f32 "
        "{%0,%1,%2,%3}, {%4,%5,%6,%7}, {%8,%9}, {%0,%1,%2,%3};"
        : "+f"(d[0]), "+f"(d[1]), "+f"(d[2]), "+f"(d[3])
        : "r"(a[0]), "r"(a[1]), "r"(a[2]), "r"(a[3]), "r"(b[0]), "r"(b[1]));
}
__device__ __forceinline__ uint32_t pack_bf2(__nv_bfloat16 lo, __nv_bfloat16 hi) {
    __nv_bfloat162 t; t.x = lo; t.y = hi;
    return *(uint32_t*)&t;
}

// ---------------- Fused projection kernel ----------------
// grid = B*64 = 512 blocks, 256 threads. Each block: 64 pixels.
// Computes v (all 128 out-channels) AND q/k (16 dims each) for its pixels,
// reading x exactly once through smem.
__global__ void proj_kernel(const float* __restrict__ x,
                            const float* __restrict__ Wq, const float* __restrict__ bq,
                            const float* __restrict__ Wk, const float* __restrict__ bk,
                            const float* __restrict__ Wv, const float* __restrict__ bv) {
    __shared__ float wv_s[32 * 132];   // [cc][oc] padded
    __shared__ float xs[32 * 64];      // [cc][pixel]
    __shared__ float wq_s[32 * 16];    // [cc][a]
    __shared__ float wk_s[32 * 16];
    int tid = threadIdx.x;
    int b = blockIdx.x >> 6;
    int n0 = (blockIdx.x & 63) << 6;
    int n_local = tid & 63;
    int cg = tid >> 6;                 // 0..3

    float acc[32];
#pragma unroll
    for (int i = 0; i < 32; i++) acc[i] = bv[cg * 32 + i];
    float qa[4], ka[4];
#pragma unroll
    for (int j = 0; j < 4; j++) { qa[j] = bq[cg * 4 + j]; ka[j] = bk[cg * 4 + j]; }

    for (int ch = 0; ch < 4; ch++) {
        int c0 = ch * 32;
        __syncthreads();
        for (int i = tid; i < 4096; i += 256) {
            int cc = i & 31, oc = i >> 5;
            wv_s[cc * 132 + oc] = Wv[oc * CC + c0 + cc];
        }
        for (int i = tid; i < 512; i += 256) {
            int a = i & 15, cc = i >> 4;
            wq_s[cc * 16 + a] = Wq[a * CC + c0 + cc];
            wk_s[cc * 16 + a] = Wk[a * CC + c0 + cc];
        }
        for (int i = tid; i < 2048; i += 256) {
            int n = i & 63, cc = i >> 6;
            xs[cc * 64 + n] = x[((size_t)b * CC + c0 + cc) * NNPIX + n0 + n];
        }
        __syncthreads();
#pragma unroll 4
        for (int cc = 0; cc < 32; cc++) {
            float xv = xs[cc * 64 + n_local];
            const float4* w4 = (const float4*)(wv_s + cc * 132 + cg * 32);
#pragma unroll
            for (int j = 0; j < 8; j++) {
                float4 w = w4[j];
                acc[4 * j + 0] += w.x * xv; acc[4 * j + 1] += w.y * xv;
                acc[4 * j + 2] += w.z * xv; acc[4 * j + 3] += w.w * xv;
            }
            float4 wq4 = *(const float4*)(wq_s + cc * 16 + cg * 4);
            float4 wk4 = *(const float4*)(wk_s + cc * 16 + cg * 4);
            qa[0] += wq4.x * xv; qa[1] += wq4.y * xv; qa[2] += wq4.z * xv; qa[3] += wq4.w * xv;
            ka[0] += wk4.x * xv; ka[1] += wk4.y * xv; ka[2] += wk4.z * xv; ka[3] += wk4.w * xv;
        }
    }

    // v writes (transposed hi/lo planes)
    __nv_bfloat16* vh = (__nv_bfloat16*)g_vth;
    __nv_bfloat16* vl = (__nv_bfloat16*)g_vtl;
#pragma unroll
    for (int i = 0; i < 32; i++) {
        int c = cg * 32 + i;
        size_t idx = ((size_t)b * CC + c) * NNPIX + n0 + n_local;
        __nv_bfloat16 h = __float2bfloat16(acc[i]);
        vh[idx] = h;
        vl[idx] = __float2bfloat16(acc[i] - __bfloat162float(h));
    }

    // q/k writes: thread owns a-dims [cg*4, cg*4+4) of pixel n_local.
    // Row layout: bytes [0,32) = 16 hi bf16, [32,64) = 16 lo bf16.
    {
        char* qrow = (char*)(g_qpack + ((size_t)b * NNPIX + n0 + n_local) * 4);
        char* krow = (char*)(g_kpack + ((size_t)b * NNPIX + n0 + n_local) * 4);
        __nv_bfloat16 qh[4], ql[4], kh[4], kl[4];
#pragma unroll
        for (int j = 0; j < 4; j++) {
            qh[j] = __float2bfloat16(qa[j]);
            ql[j] = __float2bfloat16(qa[j] - __bfloat162float(qh[j]));
            kh[j] = __float2bfloat16(ka[j]);
            kl[j] = __float2bfloat16(ka[j] - __bfloat162float(kh[j]));
        }
        *(uint2*)(qrow + cg * 8)      = make_uint2(pack_bf2(qh[0], qh[1]), pack_bf2(qh[2], qh[3]));
        *(uint2*)(qrow + 32 + cg * 8) = make_uint2(pack_bf2(ql[0], ql[1]), pack_bf2(ql[2], ql[3]));
        *(uint2*)(krow + cg * 8)      = make_uint2(pack_bf2(kh[0], kh[1]), pack_bf2(kh[2], kh[3]));
        *(uint2*)(krow + 32 + cg * 8) = make_uint2(pack_bf2(kl[0], kl[1]), pack_bf2(kl[2], kl[3]));
    }
}

// ---------------- HMMA flash attention (single-stage, occupancy 3) ----------------
// grid = B*64 = 512 CTAs, 128 threads (4 warps x 16 queries).
// smem strides: Q/K rows 80B (64B data + 16 pad), V rows 144B (128B data + 16 pad).
#define OQ   0
#define OK_  5120
#define OVH  10240
#define OVL  28672
#define SMEM_BYTES 47104

__global__ __launch_bounds__(128, 3) void attn_hmma_kernel(float* __restrict__ out) {
    __shared__ __align__(128) char sm[SMEM_BYTES];
    uint32_t sb = smem_to_u32(sm);
    int tid = threadIdx.x;
    int w = tid >> 5, lane = tid & 31;
    int b = blockIdx.x >> 6;
    int q0 = (blockIdx.x & 63) << 6;
    const float cscale = 0.25f * 1.4426950408889634f;   // scale * log2(e)

    // ---- load Q tile (64 rows x 64B packed hi|lo) ----
#pragma unroll
    for (int i = tid; i < 256; i += 128) {
        int row = i >> 2, j = i & 3;
        *(uint4*)(sm + OQ + row * 80 + j * 16) = g_qpack[((size_t)b * NNPIX + q0 + row) * 4 + j];
    }
    __syncthreads();

    // ---- Q fragments (A-operand, m16k16), hi and lo ----
    uint32_t qh[4], ql[4];
    {
        int r = (w << 4) + (lane & 7) + (((lane >> 3) & 1) << 3);
        uint32_t a = sb + OQ + r * 80 + ((lane >> 4) << 4);
        ldsm_x4(a, qh);
        ldsm_x4(a + 32, ql);
    }

    // loop-invariant lane address pieces
    uint32_t kAddr = sb + OK_ + (lane & 7) * 80 + (((lane >> 3) & 1) << 4) + ((lane >> 4) << 5);
    uint32_t vAddr = sb + (lane < 16 ? OVH : OVL) + (lane & 7) * 144 + (((lane >> 3) & 1) << 4);

    float o[16][4];
#pragma unroll
    for (int i = 0; i < 16; i++)
#pragma unroll
        for (int j = 0; j < 4; j++) o[i][j] = 0.f;
    float ls0 = 0.f, ls1 = 0.f;

    const uint4* kbase = g_kpack + (size_t)b * NNPIX * 4;
    size_t vrow = ((size_t)(b * CC + tid)) * (NNPIX / 8);

    for (int kt = 0; kt < 64; kt++) {
        __syncthreads();   // previous tile fully consumed
        // K tile: 64 rows x 64B
#pragma unroll
        for (int i = tid; i < 256; i += 128) {
            int row = i >> 2, j = i & 3;
            *(uint4*)(sm + OK_ + row * 80 + j * 16) = kbase[(size_t)kt * 256 + i];
        }
        // V tile: each thread owns channel tid, 128B hi + 128B lo
        {
            size_t vi = vrow + (size_t)kt * 8;
            char* rh = sm + OVH + tid * 144;
            char* rl = sm + OVL + tid * 144;
#pragma unroll
            for (int j = 0; j < 8; j++) {
                *(uint4*)(rh + j * 16) = g_vth[vi + j];
                *(uint4*)(rl + j * 16) = g_vtl[vi + j];
            }
        }
        __syncthreads();

        // ---- S + softmax in two halves of 4 n-tiles (keeps sc live range small) ----
        uint32_t Ph[4][4], Pl[4][4];
#pragma unroll
        for (int half = 0; half < 2; half++) {
            float sc[4][4];
#pragma unroll
            for (int i = 0; i < 4; i++) {
                int nt = half * 4 + i;
                sc[i][0] = sc[i][1] = sc[i][2] = sc[i][3] = 0.f;
                uint32_t kb[4];
                ldsm_x4(kAddr + nt * 640, kb);   // kb[0..1]=Kh frag, kb[2..3]=Kl frag
                mma16816(sc[i], qh, kb + 0);
                mma16816(sc[i], qh, kb + 2);
                mma16816(sc[i], ql, kb + 0);
            }
#pragma unroll
            for (int i = 0; i < 4; i++) {
                float p0 = ex2(sc[i][0] * cscale);
                float p1 = ex2(sc[i][1] * cscale);
                float p2 = ex2(sc[i][2] * cscale);
                float p3 = ex2(sc[i][3] * cscale);
                ls0 += p0 + p1;
                ls1 += p2 + p3;
                __nv_bfloat16 h0 = __float2bfloat16(p0), h1 = __float2bfloat16(p1);
                __nv_bfloat16 h2 = __float2bfloat16(p2), h3 = __float2bfloat16(p3);
                int kc = half * 2 + (i >> 1), hf = (i & 1) << 1;
                Ph[kc][hf + 0] = pack_bf2(h0, h1);
                Ph[kc][hf + 1] = pack_bf2(h2, h3);
                Pl[kc][hf + 0] = pack_bf2(__float2bfloat16(p0 - __bfloat162float(h0)),
                                          __float2bfloat16(p1 - __bfloat162float(h1)));
                Pl[kc][hf + 1] = pack_bf2(__float2bfloat16(p2 - __bfloat162float(h2)),
                                          __float2bfloat16(p3 - __bfloat162float(h3)));
            }
        }

        // ---- O += Ph*Vh + Ph*Vl + Pl*Vh  (16q x 128ch, K=64) ----
#pragma unroll
        for (int kc = 0; kc < 4; kc++) {
#pragma unroll
            for (int nt = 0; nt < 16; nt++) {
                uint32_t vb2[4];
                ldsm_x4(vAddr + nt * 1152 + kc * 32, vb2);  // vb2[0..1]=Vh, vb2[2..3]=Vl
                mma16816(o[nt], Ph[kc], vb2 + 0);
                mma16816(o[nt], Ph[kc], vb2 + 2);
                mma16816(o[nt], Pl[kc], vb2 + 0);
            }
        }
    }

    // ---- epilogue: row sums, normalize, store ----
    ls0 += __shfl_xor_sync(0xffffffffu, ls0, 1);
    ls0 += __shfl_xor_sync(0xffffffffu, ls0, 2);
    ls1 += __shfl_xor_sync(0xffffffffu, ls1, 1);
    ls1 += __shfl_xor_sync(0xffffffffu, ls1, 2);
    float inv0 = 1.f / ls0, inv1 = 1.f / ls1;

    int r0 = q0 + (w << 4) + (lane >> 2);
    int r1 = r0 + 8;
    float* ob = out + (size_t)b * CC * NNPIX;
#pragma unroll
    for (int nt = 0; nt < 16; nt++) {
        int c = (nt << 3) + ((lane & 3) << 1);
        ob[(size_t)c * NNPIX + r0]       = o[nt][0] * inv0;
        ob[(size_t)(c + 1) * NNPIX + r0] = o[nt][1] * inv0;
        ob[(size_t)c * NNPIX + r1]       = o[nt][2] * inv1;
        ob[(size_t)(c + 1) * NNPIX + r1] = o[nt][3] * inv1;
    }
}

// ---------------- Launch ----------------
extern "C" void kernel_launch(void* const* d_in, const int* in_sizes, int n_in,
                              void* d_out, int out_size) {
    const float* x  = (const float*)d_in[0];
    const float* Wq = (const float*)d_in[1];
    const float* bq = (const float*)d_in[2];
    const float* Wk = (const float*)d_in[3];
    const float* bk = (const float*)d_in[4];
    const float* Wv = (const float*)d_in[5];
    const float* bv = (const float*)d_in[6];
    float* out = (float*)d_out;

    proj_kernel<<<BB * (NNPIX / 64), 256>>>(x, Wq, bq, Wk, bk, Wv, bv);
    attn_hmma_kernel<<<BB * (NNPIX / 64), 128>>>(out);
}